// round 13
// baseline (speedup 1.0000x reference)
#include <cuda_runtime.h>
#include <cuda_fp16.h>
#include <math.h>
#include <stdint.h>

// Problem constants
#define BB 2
#define LL 1024
#define NN 512
#define NLAYER 2
#define DI 1024
#define SSN 16
#define KC 4
#define RR 32
#define EPS 1e-5f
#define MROWS (BB*LL)   // 2048

// Per-direction buffer sizes (elements)
#define XZ_SZ ((size_t)MROWS * 2 * DI)
#define XC_SZ ((size_t)MROWS * DI)
#define XD_SZ ((size_t)MROWS * 64)
#define YG_SZ ((size_t)MROWS * DI)

// Scratch buffers (static device globals; no runtime allocation)
__device__ __align__(256) float  g_xz  [2 * XZ_SZ];
__device__ __align__(256) float  g_xc  [2 * XC_SZ];
__device__ __align__(256) float  g_xdbl[2 * XD_SZ];
__device__ __align__(256) float  g_acc [(size_t)MROWS * NN];
__device__ __align__(256) float  g_cur [(size_t)MROWS * NN];
// fp16 operand buffers
__device__ __align__(256) __half g_xh  [(size_t)MROWS * NN];       // layer input fp16
__device__ __align__(256) __half g_inwh[(size_t)4 * 2 * DI * NN];  // in_proj weights fp16
__device__ __align__(256) __half g_owh [(size_t)4 * NN * DI];      // out_proj weights fp16
__device__ __align__(256) __half g_ygh [2 * YG_SZ];                // scan output fp16

// ===========================================================================
// Helpers
// ===========================================================================
static __device__ __forceinline__ uint32_t smem_u32(const void* p) {
    uint32_t a;
    asm("{ .reg .u64 t; cvta.to.shared.u64 t, %1; cvt.u32.u64 %0, t; }" : "=r"(a) : "l"(p));
    return a;
}

static __device__ __forceinline__ void ldsm4(uint32_t* r, uint32_t addr) {
    asm volatile("ldmatrix.sync.aligned.m8n8.x4.shared.b16 {%0,%1,%2,%3}, [%4];"
        : "=r"(r[0]), "=r"(r[1]), "=r"(r[2]), "=r"(r[3]) : "r"(addr));
}

static __device__ __forceinline__ void mma_f16(float* c, const uint32_t* a,
                                               uint32_t b0, uint32_t b1) {
    asm volatile(
        "mma.sync.aligned.m16n8k16.row.col.f32.f16.f16.f32 "
        "{%0,%1,%2,%3}, {%4,%5,%6,%7}, {%8,%9}, {%0,%1,%2,%3};"
        : "+f"(c[0]), "+f"(c[1]), "+f"(c[2]), "+f"(c[3])
        : "r"(a[0]), "r"(a[1]), "r"(a[2]), "r"(a[3]), "r"(b0), "r"(b1));
}

#define CP_ASYNC16(smem, gptr) \
    asm volatile("cp.async.cg.shared.global [%0], [%1], 16;" :: "r"(smem), "l"(gptr) : "memory")
#define CP_COMMIT() asm volatile("cp.async.commit_group;" ::: "memory")

// ===========================================================================
// Pure fp16 NT GEMM, cp.async direct into padded tiles (no convert phase).
// C[M,N] (+)= A[M,K] @ B[N,K]^T, fp16 in / fp32 out. Block 128x128, 8 warps.
// blockIdx.z = dir*nsplit + kslice; per-dir strides aZ/bZ/cZ (elements).
// epi: 0 = store, 2 = atomicAdd
// ===========================================================================
#define PADH 40
#define TILEB (128 * PADH * 2)   // 10240 bytes per fp16 tile

__global__ void __launch_bounds__(256, 2) hgemm_f16(
    const __half* __restrict__ A, const __half* __restrict__ Bw, float* __restrict__ C,
    int K, int lda, int ldb, int ldc, int epi, int nsplit,
    size_t aZ, size_t bZ, size_t cZ)
{
    __shared__ __align__(16) __half sm[2][2][128 * PADH];  // [stage][tile(A,B)]

    const int tid = threadIdx.x;
    const int wid = tid >> 5, lane = tid & 31;
    const int wm = wid >> 2, wn = wid & 3;
    const int bm = blockIdx.y * 128, bn = blockIdx.x * 128;
    const int dir = blockIdx.z / nsplit;
    const int ksl = blockIdx.z % nsplit;
    A  += (size_t)dir * aZ;
    Bw += (size_t)dir * bZ;
    C  += (size_t)dir * cZ;
    const int kslice = K / nsplit;
    const int kbeg = ksl * kslice;
    const int nch = kslice / 32;

    const uint32_t base = smem_u32(sm);
    const int lrow = lane & 15;
    const int lchunk = lane >> 4;

    float acc[4][4][4];
#pragma unroll
    for (int i = 0; i < 4; i++)
#pragma unroll
        for (int j = 0; j < 4; j++)
#pragma unroll
            for (int q = 0; q < 4; q++) acc[i][j][q] = 0.f;

    auto issue_chunk = [&](int kc, int buf) {
        const __half* Ab = A + (size_t)bm * lda + kbeg + kc * 32;
        const __half* Bb = Bw + (size_t)bn * ldb + kbeg + kc * 32;
#pragma unroll
        for (int i = 0; i < 4; i++) {
            int op = tid + i * 256;          // 0..1023
            int tile = op >> 9;              // 0 = A, 1 = B
            int rem = op & 511;
            int r = rem >> 2, seg = rem & 3; // 4 x 16B segments per 64B row
            const __half* src = (tile ? Bb + (size_t)r * ldb : Ab + (size_t)r * lda) + seg * 8;
            uint32_t dst = base + (uint32_t)(buf * 2 + tile) * TILEB
                         + (uint32_t)(r * PADH + seg * 8) * 2;
            CP_ASYNC16(dst, src);
        }
        CP_COMMIT();
    };

    issue_chunk(0, 0);

    for (int kc = 0; kc < nch; kc++) {
        if (kc + 1 < nch) {
            issue_chunk(kc + 1, (kc + 1) & 1);
            asm volatile("cp.async.wait_group 1;" ::: "memory");
        } else {
            asm volatile("cp.async.wait_group 0;" ::: "memory");
        }
        __syncthreads();

        const uint32_t aA = base + (uint32_t)((kc & 1) * 2) * TILEB;
        const uint32_t aB = aA + TILEB;

#pragma unroll
        for (int ks = 0; ks < 2; ks++) {
            uint32_t ah[4][4];
#pragma unroll
            for (int mt = 0; mt < 4; mt++) {
                uint32_t off = (uint32_t)((wm * 64 + mt * 16 + lrow) * PADH
                                          + ks * 16 + lchunk * 8) * 2;
                ldsm4(ah[mt], aA + off);
            }
            uint32_t bh[2][4];
#pragma unroll
            for (int np = 0; np < 2; np++) {
                uint32_t off = (uint32_t)((wn * 32 + np * 16 + lrow) * PADH
                                          + ks * 16 + lchunk * 8) * 2;
                ldsm4(bh[np], aB + off);
            }
#pragma unroll
            for (int mt = 0; mt < 4; mt++)
#pragma unroll
                for (int np = 0; np < 2; np++)
#pragma unroll
                    for (int sub = 0; sub < 2; sub++) {
                        int nt = np * 2 + sub;
                        mma_f16(acc[mt][nt], ah[mt], bh[np][sub], bh[np][sub + 2]);
                    }
        }
        __syncthreads();   // tiles consumed; next issue into this stage is safe
    }

    // Epilogue
    const int r0 = lane >> 2;
    const int c0 = (lane & 3) * 2;
#pragma unroll
    for (int mt = 0; mt < 4; mt++) {
#pragma unroll
        for (int nt = 0; nt < 4; nt++) {
            int m = bm + wm * 64 + mt * 16 + r0;
            int n = bn + wn * 32 + nt * 8 + c0;
            float* p0 = &C[(size_t)m * ldc + n];
            float* p1 = &C[(size_t)(m + 8) * ldc + n];
            float* a = acc[mt][nt];
            if (epi == 0) {
                *(float2*)p0 = make_float2(a[0], a[1]);
                *(float2*)p1 = make_float2(a[2], a[3]);
            } else {
                atomicAdd(p0, a[0]); atomicAdd(p0 + 1, a[1]);
                atomicAdd(p1, a[2]); atomicAdd(p1 + 1, a[3]);
            }
        }
    }
}

// ===========================================================================
// CUDA-core SGEMM (xproj): split-K + atomicAdd. blockIdx.z = dir*nsplit + slice.
// ===========================================================================
template<int BM, int BN, int BK, int TM, int TN>
__global__ void sgemm_nt(const float* __restrict__ A, const float* __restrict__ Bm,
                         float* __restrict__ C, int M, int N, int Kt,
                         int lda, int ldb, int ldc, int nsplit,
                         size_t aZ, size_t bZ, size_t cZ)
{
    constexpr int TX = BN / TN;
    constexpr int TY = BM / TM;
    constexpr int THREADS = TX * TY;
    __shared__ float As[BK][BM + 4];
    __shared__ float Bs[BK][BN + 4];

    const int tid = threadIdx.x;
    const int tx = tid % TX;
    const int ty = tid / TX;
    const int bm = blockIdx.y * BM;
    const int bn = blockIdx.x * BN;
    const int dir = blockIdx.z / nsplit;
    const int ksl = blockIdx.z % nsplit;
    A += (size_t)dir * aZ;
    Bm += (size_t)dir * bZ;
    C += (size_t)dir * cZ;
    const int kslice = Kt / nsplit;
    const int kbeg = ksl * kslice;
    const int kend = kbeg + kslice;

    float acc[TM][TN];
#pragma unroll
    for (int m = 0; m < TM; m++)
#pragma unroll
        for (int n = 0; n < TN; n++) acc[m][n] = 0.f;

    for (int k0 = kbeg; k0 < kend; k0 += BK) {
#pragma unroll
        for (int i = 0; i < BM * BK / 4 / THREADS; i++) {
            int idx = tid + i * THREADS;
            int r = idx / (BK / 4);
            int c4 = idx % (BK / 4);
            float4 v = *(const float4*)&A[(size_t)(bm + r) * lda + k0 + c4 * 4];
            As[c4 * 4 + 0][r] = v.x;
            As[c4 * 4 + 1][r] = v.y;
            As[c4 * 4 + 2][r] = v.z;
            As[c4 * 4 + 3][r] = v.w;
        }
#pragma unroll
        for (int i = 0; i < BN * BK / 4 / THREADS; i++) {
            int idx = tid + i * THREADS;
            int r = idx / (BK / 4);
            int c4 = idx % (BK / 4);
            float4 v = *(const float4*)&Bm[(size_t)(bn + r) * ldb + k0 + c4 * 4];
            Bs[c4 * 4 + 0][r] = v.x;
            Bs[c4 * 4 + 1][r] = v.y;
            Bs[c4 * 4 + 2][r] = v.z;
            Bs[c4 * 4 + 3][r] = v.w;
        }
        __syncthreads();

#pragma unroll
        for (int k = 0; k < BK; k++) {
            float ra[TM], rb[TN];
#pragma unroll
            for (int m = 0; m < TM; m++) ra[m] = As[k][ty * TM + m];
#pragma unroll
            for (int n = 0; n < TN; n++) rb[n] = Bs[k][tx * TN + n];
#pragma unroll
            for (int m = 0; m < TM; m++)
#pragma unroll
                for (int n = 0; n < TN; n++)
                    acc[m][n] = fmaf(ra[m], rb[n], acc[m][n]);
        }
        __syncthreads();
    }

#pragma unroll
    for (int m = 0; m < TM; m++) {
        int r = bm + ty * TM + m;
#pragma unroll
        for (int n = 0; n < TN; n++) {
            int c = bn + tx * TN + n;
            atomicAdd(&C[(size_t)r * ldc + c], acc[m][n]);
        }
    }
}

// ===========================================================================
// Causal depthwise conv (K=4) + SiLU, float4 over d. blockIdx.y = dir.
// ===========================================================================
__global__ void conv_silu_kernel(const float* __restrict__ xz,
                                 const float* __restrict__ cw,
                                 const float* __restrict__ cb,
                                 float* __restrict__ xc)
{
    const int dir = blockIdx.y;
    xz += (size_t)dir * XZ_SZ;
    cw += (size_t)dir * DI * KC;
    cb += (size_t)dir * DI;
    xc += (size_t)dir * XC_SZ;
    const int rev = dir;

    int idx = blockIdx.x * blockDim.x + threadIdx.x;   // over B*L*DI/4
    if (idx >= BB * LL * DI / 4) return;
    int d4 = (idx % (DI / 4)) * 4;
    int l  = (idx / (DI / 4)) % LL;
    int b  = idx / ((DI / 4) * LL);

    float4 acc = *(const float4*)(cb + d4);
    float4 w0 = *(const float4*)(cw + (d4 + 0) * KC);
    float4 w1 = *(const float4*)(cw + (d4 + 1) * KC);
    float4 w2 = *(const float4*)(cw + (d4 + 2) * KC);
    float4 w3 = *(const float4*)(cw + (d4 + 3) * KC);
    const float wk0[4] = {w0.x, w0.y, w0.z, w0.w};
    const float wk1[4] = {w1.x, w1.y, w1.z, w1.w};
    const float wk2[4] = {w2.x, w2.y, w2.z, w2.w};
    const float wk3[4] = {w3.x, w3.y, w3.z, w3.w};

#pragma unroll
    for (int k = 0; k < KC; k++) {
        int lp = rev ? (l + (KC - 1) - k) : (l - (KC - 1) + k);
        if (lp >= 0 && lp < LL) {
            float4 v = *(const float4*)(xz + ((size_t)(b * LL + lp)) * 2 * DI + d4);
            acc.x = fmaf(wk0[k], v.x, acc.x);
            acc.y = fmaf(wk1[k], v.y, acc.y);
            acc.z = fmaf(wk2[k], v.z, acc.z);
            acc.w = fmaf(wk3[k], v.w, acc.w);
        }
    }
    acc.x *= 1.f / (1.f + __expf(-acc.x));
    acc.y *= 1.f / (1.f + __expf(-acc.y));
    acc.z *= 1.f / (1.f + __expf(-acc.z));
    acc.w *= 1.f / (1.f + __expf(-acc.w));
    *(float4*)(xc + (size_t)idx * 4) = acc;
}

// ===========================================================================
// Fused dtproj + softplus + selective scan + C-dot + D skip + SiLU(z) gate.
// Writes yg as fp16 (consumed only by out_proj hgemm_f16).
// ===========================================================================
#define SCH 32
#define SCD 16

__global__ void __launch_bounds__(256) scan_kernel(
                            const float* __restrict__ xc,
                            const float* __restrict__ xz,
                            const float* __restrict__ xdbl,
                            const float* __restrict__ Alog,
                            const float* __restrict__ Dp,
                            const float* __restrict__ dtw,
                            const float* __restrict__ dtb,
                            __half* __restrict__ yg)
{
    __shared__ float2 s_dx[SCH][SCD];
    __shared__ float  s_z [SCH][SCD];
    __shared__ float2 s_bc[SCH][SSN];
    __shared__ float  s_c [SCH][SCD][SSN + 1];
    float (*s_raw)[RR] = (float (*)[RR])(&s_c[0][0][0]);  // overlay, disjoint phases

    const int tid = threadIdx.x;
    const int cd = tid >> 4;
    const int s  = tid & 15;
    const int d0 = blockIdx.x * SCD;
    const int b  = blockIdx.y;
    const int dir = blockIdx.z;
    const int rev = dir;
    const int d  = d0 + cd;

    xc   += (size_t)dir * XC_SZ;
    xz   += (size_t)dir * XZ_SZ;
    xdbl += (size_t)dir * XD_SZ;
    yg   += (size_t)dir * YG_SZ;
    Alog += (size_t)dir * DI * SSN;
    Dp   += (size_t)dir * DI;
    dtw  += (size_t)dir * DI * RR;
    dtb  += (size_t)dir * DI;

    const float Aneg = -__expf(Alog[(size_t)d * SSN + s]);

    const int mydl = tid & 15;
    const float myD = Dp[d0 + mydl];
    float wdt[RR];
#pragma unroll
    for (int k = 0; k < RR; k++) wdt[k] = dtw[(size_t)(d0 + mydl) * RR + k];
    const float mydtb = dtb[d0 + mydl];

    float h = 0.f;

    for (int t0 = 0; t0 < LL; t0 += SCH) {
#pragma unroll
        for (int it = 0; it < SCH * SCD / 256; it++) {
            int idx = tid + it * 256;
            int j = idx / SCD, dl = idx % SCD;
            int p = rev ? (LL - 1 - (t0 + j)) : (t0 + j);
            size_t row = (size_t)(b * LL + p);
            s_dx[j][dl].y = xc[row * DI + d0 + dl];
            s_z [j][dl]   = xz[row * 2 * DI + DI + d0 + dl];
        }
#pragma unroll
        for (int it = 0; it < SCH * 64 / 256; it++) {
            int idx = tid + it * 256;
            int j = idx / 64, c = idx % 64;
            int p = rev ? (LL - 1 - (t0 + j)) : (t0 + j);
            float v = xdbl[(size_t)(b * LL + p) * 64 + c];
            if (c < RR)            s_raw[j][c] = v;
            else if (c < RR + SSN) s_bc[j][c - RR].x = v;
            else                   s_bc[j][c - RR - SSN].y = v;
        }
        __syncthreads();

#pragma unroll
        for (int it = 0; it < SCH * SCD / 256; it++) {
            int idx = tid + it * 256;
            int j = idx / SCD;
            float u = mydtb;
#pragma unroll
            for (int k = 0; k < RR; k++) u = fmaf(s_raw[j][k], wdt[k], u);
            float sp = (u > 0.f) ? (u + log1pf(__expf(-u))) : log1pf(__expf(u));
            s_dx[j][mydl].x = sp;
        }
        __syncthreads();

#pragma unroll 8
        for (int j = 0; j < SCH; j++) {
            float2 dx = s_dx[j][cd];
            float2 bc = s_bc[j][s];
            float dA = __expf(dx.x * Aneg);
            h = fmaf(dA, h, dx.x * dx.y * bc.x);
            s_c[j][cd][s] = h * bc.y;
        }
        __syncthreads();

#pragma unroll
        for (int it = 0; it < SCH * SCD / 256; it++) {
            int idx = tid + it * 256;
            int j = idx / SCD, dl = idx % SCD;
            float sum = 0.f;
#pragma unroll
            for (int ss = 0; ss < SSN; ss++) sum += s_c[j][dl][ss];
            float y = fmaf(s_dx[j][dl].y, myD, sum);
            float zv = s_z[j][dl];
            y *= zv / (1.f + __expf(-zv));
            int p = rev ? (LL - 1 - (t0 + j)) : (t0 + j);
            yg[(size_t)(b * LL + p) * DI + d0 + dl] = __float2half(y);
        }
        __syncthreads();
    }
}

// ===========================================================================
// LayerNorm (optional fp16 copy of output), copy, zero, f2h convert
// ===========================================================================
__global__ void layernorm_kernel(const float* __restrict__ acc,
                                 const float* __restrict__ g,
                                 const float* __restrict__ bta,
                                 float* __restrict__ out,
                                 __half* __restrict__ out_h)
{
    __shared__ float red[256];
    int row = blockIdx.x;
    int t = threadIdx.x;
    const float* rp = acc + (size_t)row * NN;

    float v0 = rp[t];
    float v1 = rp[t + 256];

    red[t] = v0 + v1;
    __syncthreads();
    for (int o = 128; o > 0; o >>= 1) {
        if (t < o) red[t] += red[t + o];
        __syncthreads();
    }
    float mu = red[0] * (1.f / NN);
    __syncthreads();

    float c0 = v0 - mu, c1 = v1 - mu;
    red[t] = c0 * c0 + c1 * c1;
    __syncthreads();
    for (int o = 128; o > 0; o >>= 1) {
        if (t < o) red[t] += red[t + o];
        __syncthreads();
    }
    float inv = rsqrtf(red[0] * (1.f / NN) + EPS);

    float r0 = c0 * inv * g[t]       + bta[t];
    float r1 = c1 * inv * g[t + 256] + bta[t + 256];
    float* op = out + (size_t)row * NN;
    op[t]       = r0;
    op[t + 256] = r1;
    if (out_h) {
        __half* oh = out_h + (size_t)row * NN;
        oh[t]       = __float2half(r0);
        oh[t + 256] = __float2half(r1);
    }
}

__global__ void copy_kernel(float* __restrict__ dst, const float* __restrict__ src, int n4)
{
    int i = blockIdx.x * blockDim.x + threadIdx.x;
    if (i < n4) ((float4*)dst)[i] = ((const float4*)src)[i];
}

__global__ void zero_kernel(float* __restrict__ dst, int n4)
{
    int i = blockIdx.x * blockDim.x + threadIdx.x;
    if (i < n4) ((float4*)dst)[i] = make_float4(0.f, 0.f, 0.f, 0.f);
}

__global__ void f2h_kernel(const float* __restrict__ src, __half* __restrict__ dst, int n4)
{
    for (int i = blockIdx.x * blockDim.x + threadIdx.x; i < n4; i += gridDim.x * blockDim.x) {
        float4 v = ((const float4*)src)[i];
        ((__half2*)dst)[2 * i]     = __floats2half2_rn(v.x, v.y);
        ((__half2*)dst)[2 * i + 1] = __floats2half2_rn(v.z, v.w);
    }
}

// ===========================================================================
extern "C" void kernel_launch(void* const* d_in, const int* in_sizes, int n_in,
                              void* d_out, int out_size)
{
    const float* x    = (const float*)d_in[0];
    const float* inw  = (const float*)d_in[1];
    const float* cw   = (const float*)d_in[2];
    const float* cb   = (const float*)d_in[3];
    const float* xw   = (const float*)d_in[4];
    const float* dtw  = (const float*)d_in[5];
    const float* dtb  = (const float*)d_in[6];
    const float* Alog = (const float*)d_in[7];
    const float* Dp   = (const float*)d_in[8];
    const float* ow   = (const float*)d_in[9];
    const float* lng  = (const float*)d_in[10];
    const float* lnb  = (const float*)d_in[11];

    float *xz, *xc, *xdbl, *acc, *cur;
    __half *xh, *inwh, *owh, *ygh;
    cudaGetSymbolAddress((void**)&xz,   g_xz);
    cudaGetSymbolAddress((void**)&xc,   g_xc);
    cudaGetSymbolAddress((void**)&xdbl, g_xdbl);
    cudaGetSymbolAddress((void**)&acc,  g_acc);
    cudaGetSymbolAddress((void**)&cur,  g_cur);
    cudaGetSymbolAddress((void**)&xh,   g_xh);
    cudaGetSymbolAddress((void**)&inwh, g_inwh);
    cudaGetSymbolAddress((void**)&owh,  g_owh);
    cudaGetSymbolAddress((void**)&ygh,  g_ygh);

    // One-pass fp16 conversion of weights and initial input
    f2h_kernel<<<592, 256>>>(inw, inwh, (int)(4 * 2 * DI * NN / 4));
    f2h_kernel<<<592, 256>>>(ow,  owh,  (int)(4 * NN * DI / 4));
    f2h_kernel<<<592, 256>>>(x,   xh,   (int)(MROWS * NN / 4));

    const float* layer_in = x;

    for (int l = 0; l < NLAYER; l++) {
        const size_t i0 = 2 * l;  // weight index of fwd direction

        // acc = residual
        copy_kernel<<<(MROWS * NN / 4 + 255) / 256, 256>>>(acc, layer_in, MROWS * NN / 4);

        // in_proj, both dirs: xz[dir] = xh @ inwh[i0+dir]^T (pure fp16 operands)
        hgemm_f16<<<dim3(2 * DI / 128, MROWS / 128, 2), 256>>>(
            xh, inwh + i0 * 2 * DI * NN, xz,
            NN, NN, NN, 2 * DI, /*epi*/0, /*nsplit*/1,
            0, (size_t)2 * DI * NN, XZ_SZ);

        // conv + SiLU, both dirs
        conv_silu_kernel<<<dim3((BB * LL * DI / 4 + 255) / 256, 2), 256>>>(
            xz, cw + i0 * DI * KC, cb + i0 * DI, xc);

        // xproj, both dirs, split-K=8 + atomics
        zero_kernel<<<(2 * (int)XD_SZ / 4 + 255) / 256, 256>>>(xdbl, 2 * (int)XD_SZ / 4);
        sgemm_nt<64, 64, 16, 4, 4><<<dim3(1, MROWS / 64, 16), 256>>>(
            xc, xw + i0 * 64 * DI, xdbl,
            MROWS, 64, DI, DI, DI, 64, /*nsplit*/8,
            XC_SZ, (size_t)64 * DI, XD_SZ);

        // fused dtproj + scan + gate, both dirs -> fp16 yg
        scan_kernel<<<dim3(DI / SCD, BB, 2), 256>>>(
            xc, xz, xdbl,
            Alog + i0 * DI * SSN, Dp + i0 * DI,
            dtw + i0 * DI * RR, dtb + i0 * DI, ygh);

        // out_proj, both dirs x split-K=2, atomic into residual (fp16 operands)
        hgemm_f16<<<dim3(NN / 128, MROWS / 128, 4), 256>>>(
            ygh, owh + i0 * NN * DI, acc,
            DI, DI, DI, NN, /*epi*/2, /*nsplit*/2,
            YG_SZ, (size_t)NN * DI, 0);

        // LayerNorm; intermediate layer also emits fp16 input for next in_proj
        float* lnout = (l == NLAYER - 1) ? (float*)d_out : cur;
        __half* lnout_h = (l == NLAYER - 1) ? (__half*)nullptr : xh;
        layernorm_kernel<<<MROWS, 256>>>(acc, lng + (size_t)l * NN, lnb + (size_t)l * NN,
                                         lnout, lnout_h);
        layer_in = cur;
    }
}

// round 14
// speedup vs baseline: 1.0003x; 1.0003x over previous
#include <cuda_runtime.h>
#include <cuda_fp16.h>
#include <math.h>
#include <stdint.h>

// Problem constants
#define BB 2
#define LL 1024
#define NN 512
#define NLAYER 2
#define DI 1024
#define SSN 16
#define KC 4
#define RR 32
#define EPS 1e-5f
#define MROWS (BB*LL)   // 2048

// Per-direction buffer sizes (elements)
#define XZ_SZ ((size_t)MROWS * 2 * DI)
#define XC_SZ ((size_t)MROWS * DI)
#define XD_SZ ((size_t)MROWS * 64)
#define YG_SZ ((size_t)MROWS * DI)

// Scratch buffers (static device globals; no runtime allocation)
__device__ __align__(256) float  g_xz  [2 * XZ_SZ];
__device__ __align__(256) float  g_xc  [2 * XC_SZ];
__device__ __align__(256) float  g_xdbl[2 * XD_SZ];
__device__ __align__(256) float  g_acc [(size_t)MROWS * NN];
__device__ __align__(256) float  g_cur [(size_t)MROWS * NN];
// fp16 operand buffers
__device__ __align__(256) __half g_xh  [(size_t)MROWS * NN];
__device__ __align__(256) __half g_inwh[(size_t)4 * 2 * DI * NN];
__device__ __align__(256) __half g_owh [(size_t)4 * NN * DI];
__device__ __align__(256) __half g_ygh [2 * YG_SZ];

// ===========================================================================
// Helpers
// ===========================================================================
static __device__ __forceinline__ uint32_t smem_u32(const void* p) {
    uint32_t a;
    asm("{ .reg .u64 t; cvta.to.shared.u64 t, %1; cvt.u32.u64 %0, t; }" : "=r"(a) : "l"(p));
    return a;
}

static __device__ __forceinline__ void ldsm4(uint32_t* r, uint32_t addr) {
    asm volatile("ldmatrix.sync.aligned.m8n8.x4.shared.b16 {%0,%1,%2,%3}, [%4];"
        : "=r"(r[0]), "=r"(r[1]), "=r"(r[2]), "=r"(r[3]) : "r"(addr));
}

static __device__ __forceinline__ void mma_f16(float* c, const uint32_t* a,
                                               uint32_t b0, uint32_t b1) {
    asm volatile(
        "mma.sync.aligned.m16n8k16.row.col.f32.f16.f16.f32 "
        "{%0,%1,%2,%3}, {%4,%5,%6,%7}, {%8,%9}, {%0,%1,%2,%3};"
        : "+f"(c[0]), "+f"(c[1]), "+f"(c[2]), "+f"(c[3])
        : "r"(a[0]), "r"(a[1]), "r"(a[2]), "r"(a[3]), "r"(b0), "r"(b1));
}

#define CP_ASYNC16(smem, gptr) \
    asm volatile("cp.async.cg.shared.global [%0], [%1], 16;" :: "r"(smem), "l"(gptr) : "memory")
#define CP_COMMIT() asm volatile("cp.async.commit_group;" ::: "memory")

// ===========================================================================
// Pure fp16 NT GEMM, 3-stage cp.async pipeline, ONE __syncthreads per chunk.
// C[M,N] (+)= A[M,K] @ B[N,K]^T, fp16 in / fp32 out. Block 128x128, 8 warps.
// blockIdx.z = dir*nsplit + kslice; per-dir strides aZ/bZ/cZ (elements).
// epi: 0 = store, 2 = atomicAdd
// ===========================================================================
#define PADH 40
#define TILEB (128 * PADH * 2)          // 10240 bytes per fp16 tile
#define NSTAGE 3
#define HG_SMEM (NSTAGE * 2 * TILEB)    // 61440 bytes

__global__ void __launch_bounds__(256, 2) hgemm_f16(
    const __half* __restrict__ A, const __half* __restrict__ Bw, float* __restrict__ C,
    int K, int lda, int ldb, int ldc, int epi, int nsplit,
    size_t aZ, size_t bZ, size_t cZ)
{
    extern __shared__ __align__(16) char dsm[];

    const int tid = threadIdx.x;
    const int wid = tid >> 5, lane = tid & 31;
    const int wm = wid >> 2, wn = wid & 3;
    const int bm = blockIdx.y * 128, bn = blockIdx.x * 128;
    const int dir = blockIdx.z / nsplit;
    const int ksl = blockIdx.z % nsplit;
    A  += (size_t)dir * aZ;
    Bw += (size_t)dir * bZ;
    C  += (size_t)dir * cZ;
    const int kslice = K / nsplit;
    const int kbeg = ksl * kslice;
    const int nch = kslice / 32;

    const uint32_t base = smem_u32(dsm);
    const int lrow = lane & 15;
    const int lchunk = lane >> 4;

    float acc[4][4][4];
#pragma unroll
    for (int i = 0; i < 4; i++)
#pragma unroll
        for (int j = 0; j < 4; j++)
#pragma unroll
            for (int q = 0; q < 4; q++) acc[i][j][q] = 0.f;

    auto issue_chunk = [&](int kc, int stg) {
        const __half* Ab = A + (size_t)bm * lda + kbeg + kc * 32;
        const __half* Bb = Bw + (size_t)bn * ldb + kbeg + kc * 32;
#pragma unroll
        for (int i = 0; i < 4; i++) {
            int op = tid + i * 256;          // 0..1023
            int tile = op >> 9;              // 0 = A, 1 = B
            int rem = op & 511;
            int r = rem >> 2, seg = rem & 3; // 4 x 16B segments per 64B row
            const __half* src = (tile ? Bb + (size_t)r * ldb : Ab + (size_t)r * lda) + seg * 8;
            uint32_t dst = base + (uint32_t)(stg * 2 + tile) * TILEB
                         + (uint32_t)(r * PADH + seg * 8) * 2;
            CP_ASYNC16(dst, src);
        }
        CP_COMMIT();
    };

    issue_chunk(0, 0);
    if (nch > 1) issue_chunk(1, 1);

    for (int kc = 0; kc < nch; kc++) {
        if (kc + 1 < nch) {
            asm volatile("cp.async.wait_group 1;" ::: "memory");
        } else {
            asm volatile("cp.async.wait_group 0;" ::: "memory");
        }
        __syncthreads();   // chunk kc visible to all; stage (kc+2)%3 fully consumed

        if (kc + 2 < nch) issue_chunk(kc + 2, (kc + 2) % NSTAGE);

        const uint32_t aA = base + (uint32_t)((kc % NSTAGE) * 2) * TILEB;
        const uint32_t aB = aA + TILEB;

#pragma unroll
        for (int ks = 0; ks < 2; ks++) {
            uint32_t ah[4][4];
#pragma unroll
            for (int mt = 0; mt < 4; mt++) {
                uint32_t off = (uint32_t)((wm * 64 + mt * 16 + lrow) * PADH
                                          + ks * 16 + lchunk * 8) * 2;
                ldsm4(ah[mt], aA + off);
            }
            uint32_t bh[2][4];
#pragma unroll
            for (int np = 0; np < 2; np++) {
                uint32_t off = (uint32_t)((wn * 32 + np * 16 + lrow) * PADH
                                          + ks * 16 + lchunk * 8) * 2;
                ldsm4(bh[np], aB + off);
            }
#pragma unroll
            for (int mt = 0; mt < 4; mt++)
#pragma unroll
                for (int np = 0; np < 2; np++)
#pragma unroll
                    for (int sub = 0; sub < 2; sub++) {
                        int nt = np * 2 + sub;
                        mma_f16(acc[mt][nt], ah[mt], bh[np][sub], bh[np][sub + 2]);
                    }
        }
    }

    // Epilogue
    const int r0 = lane >> 2;
    const int c0 = (lane & 3) * 2;
#pragma unroll
    for (int mt = 0; mt < 4; mt++) {
#pragma unroll
        for (int nt = 0; nt < 4; nt++) {
            int m = bm + wm * 64 + mt * 16 + r0;
            int n = bn + wn * 32 + nt * 8 + c0;
            float* p0 = &C[(size_t)m * ldc + n];
            float* p1 = &C[(size_t)(m + 8) * ldc + n];
            float* a = acc[mt][nt];
            if (epi == 0) {
                *(float2*)p0 = make_float2(a[0], a[1]);
                *(float2*)p1 = make_float2(a[2], a[3]);
            } else {
                atomicAdd(p0, a[0]); atomicAdd(p0 + 1, a[1]);
                atomicAdd(p1, a[2]); atomicAdd(p1 + 1, a[3]);
            }
        }
    }
}

// ===========================================================================
// CUDA-core SGEMM (xproj): split-K + atomicAdd. blockIdx.z = dir*nsplit + slice.
// ===========================================================================
template<int BM, int BN, int BK, int TM, int TN>
__global__ void sgemm_nt(const float* __restrict__ A, const float* __restrict__ Bm,
                         float* __restrict__ C, int M, int N, int Kt,
                         int lda, int ldb, int ldc, int nsplit,
                         size_t aZ, size_t bZ, size_t cZ)
{
    constexpr int TX = BN / TN;
    constexpr int TY = BM / TM;
    constexpr int THREADS = TX * TY;
    __shared__ float As[BK][BM + 4];
    __shared__ float Bs[BK][BN + 4];

    const int tid = threadIdx.x;
    const int tx = tid % TX;
    const int ty = tid / TX;
    const int bm = blockIdx.y * BM;
    const int bn = blockIdx.x * BN;
    const int dir = blockIdx.z / nsplit;
    const int ksl = blockIdx.z % nsplit;
    A += (size_t)dir * aZ;
    Bm += (size_t)dir * bZ;
    C += (size_t)dir * cZ;
    const int kslice = Kt / nsplit;
    const int kbeg = ksl * kslice;
    const int kend = kbeg + kslice;

    float acc[TM][TN];
#pragma unroll
    for (int m = 0; m < TM; m++)
#pragma unroll
        for (int n = 0; n < TN; n++) acc[m][n] = 0.f;

    for (int k0 = kbeg; k0 < kend; k0 += BK) {
#pragma unroll
        for (int i = 0; i < BM * BK / 4 / THREADS; i++) {
            int idx = tid + i * THREADS;
            int r = idx / (BK / 4);
            int c4 = idx % (BK / 4);
            float4 v = *(const float4*)&A[(size_t)(bm + r) * lda + k0 + c4 * 4];
            As[c4 * 4 + 0][r] = v.x;
            As[c4 * 4 + 1][r] = v.y;
            As[c4 * 4 + 2][r] = v.z;
            As[c4 * 4 + 3][r] = v.w;
        }
#pragma unroll
        for (int i = 0; i < BN * BK / 4 / THREADS; i++) {
            int idx = tid + i * THREADS;
            int r = idx / (BK / 4);
            int c4 = idx % (BK / 4);
            float4 v = *(const float4*)&Bm[(size_t)(bn + r) * ldb + k0 + c4 * 4];
            Bs[c4 * 4 + 0][r] = v.x;
            Bs[c4 * 4 + 1][r] = v.y;
            Bs[c4 * 4 + 2][r] = v.z;
            Bs[c4 * 4 + 3][r] = v.w;
        }
        __syncthreads();

#pragma unroll
        for (int k = 0; k < BK; k++) {
            float ra[TM], rb[TN];
#pragma unroll
            for (int m = 0; m < TM; m++) ra[m] = As[k][ty * TM + m];
#pragma unroll
            for (int n = 0; n < TN; n++) rb[n] = Bs[k][tx * TN + n];
#pragma unroll
            for (int m = 0; m < TM; m++)
#pragma unroll
                for (int n = 0; n < TN; n++)
                    acc[m][n] = fmaf(ra[m], rb[n], acc[m][n]);
        }
        __syncthreads();
    }

#pragma unroll
    for (int m = 0; m < TM; m++) {
        int r = bm + ty * TM + m;
#pragma unroll
        for (int n = 0; n < TN; n++) {
            int c = bn + tx * TN + n;
            atomicAdd(&C[(size_t)r * ldc + c], acc[m][n]);
        }
    }
}

// ===========================================================================
// Causal depthwise conv (K=4) + SiLU, float4 over d. blockIdx.y = dir.
// ===========================================================================
__global__ void conv_silu_kernel(const float* __restrict__ xz,
                                 const float* __restrict__ cw,
                                 const float* __restrict__ cb,
                                 float* __restrict__ xc)
{
    const int dir = blockIdx.y;
    xz += (size_t)dir * XZ_SZ;
    cw += (size_t)dir * DI * KC;
    cb += (size_t)dir * DI;
    xc += (size_t)dir * XC_SZ;
    const int rev = dir;

    int idx = blockIdx.x * blockDim.x + threadIdx.x;   // over B*L*DI/4
    if (idx >= BB * LL * DI / 4) return;
    int d4 = (idx % (DI / 4)) * 4;
    int l  = (idx / (DI / 4)) % LL;
    int b  = idx / ((DI / 4) * LL);

    float4 acc = *(const float4*)(cb + d4);
    float4 w0 = *(const float4*)(cw + (d4 + 0) * KC);
    float4 w1 = *(const float4*)(cw + (d4 + 1) * KC);
    float4 w2 = *(const float4*)(cw + (d4 + 2) * KC);
    float4 w3 = *(const float4*)(cw + (d4 + 3) * KC);
    const float wk0[4] = {w0.x, w0.y, w0.z, w0.w};
    const float wk1[4] = {w1.x, w1.y, w1.z, w1.w};
    const float wk2[4] = {w2.x, w2.y, w2.z, w2.w};
    const float wk3[4] = {w3.x, w3.y, w3.z, w3.w};

#pragma unroll
    for (int k = 0; k < KC; k++) {
        int lp = rev ? (l + (KC - 1) - k) : (l - (KC - 1) + k);
        if (lp >= 0 && lp < LL) {
            float4 v = *(const float4*)(xz + ((size_t)(b * LL + lp)) * 2 * DI + d4);
            acc.x = fmaf(wk0[k], v.x, acc.x);
            acc.y = fmaf(wk1[k], v.y, acc.y);
            acc.z = fmaf(wk2[k], v.z, acc.z);
            acc.w = fmaf(wk3[k], v.w, acc.w);
        }
    }
    acc.x *= 1.f / (1.f + __expf(-acc.x));
    acc.y *= 1.f / (1.f + __expf(-acc.y));
    acc.z *= 1.f / (1.f + __expf(-acc.z));
    acc.w *= 1.f / (1.f + __expf(-acc.w));
    *(float4*)(xc + (size_t)idx * 4) = acc;
}

// ===========================================================================
// Fused dtproj + softplus + selective scan + C-dot + D skip + SiLU(z) gate.
// Writes yg as fp16 (consumed only by out_proj hgemm_f16).
// ===========================================================================
#define SCH 32
#define SCD 16

__global__ void __launch_bounds__(256) scan_kernel(
                            const float* __restrict__ xc,
                            const float* __restrict__ xz,
                            const float* __restrict__ xdbl,
                            const float* __restrict__ Alog,
                            const float* __restrict__ Dp,
                            const float* __restrict__ dtw,
                            const float* __restrict__ dtb,
                            __half* __restrict__ yg)
{
    __shared__ float2 s_dx[SCH][SCD];
    __shared__ float  s_z [SCH][SCD];
    __shared__ float2 s_bc[SCH][SSN];
    __shared__ float  s_c [SCH][SCD][SSN + 1];
    float (*s_raw)[RR] = (float (*)[RR])(&s_c[0][0][0]);  // overlay, disjoint phases

    const int tid = threadIdx.x;
    const int cd = tid >> 4;
    const int s  = tid & 15;
    const int d0 = blockIdx.x * SCD;
    const int b  = blockIdx.y;
    const int dir = blockIdx.z;
    const int rev = dir;
    const int d  = d0 + cd;

    xc   += (size_t)dir * XC_SZ;
    xz   += (size_t)dir * XZ_SZ;
    xdbl += (size_t)dir * XD_SZ;
    yg   += (size_t)dir * YG_SZ;
    Alog += (size_t)dir * DI * SSN;
    Dp   += (size_t)dir * DI;
    dtw  += (size_t)dir * DI * RR;
    dtb  += (size_t)dir * DI;

    const float Aneg = -__expf(Alog[(size_t)d * SSN + s]);

    const int mydl = tid & 15;
    const float myD = Dp[d0 + mydl];
    float wdt[RR];
#pragma unroll
    for (int k = 0; k < RR; k++) wdt[k] = dtw[(size_t)(d0 + mydl) * RR + k];
    const float mydtb = dtb[d0 + mydl];

    float h = 0.f;

    for (int t0 = 0; t0 < LL; t0 += SCH) {
#pragma unroll
        for (int it = 0; it < SCH * SCD / 256; it++) {
            int idx = tid + it * 256;
            int j = idx / SCD, dl = idx % SCD;
            int p = rev ? (LL - 1 - (t0 + j)) : (t0 + j);
            size_t row = (size_t)(b * LL + p);
            s_dx[j][dl].y = xc[row * DI + d0 + dl];
            s_z [j][dl]   = xz[row * 2 * DI + DI + d0 + dl];
        }
#pragma unroll
        for (int it = 0; it < SCH * 64 / 256; it++) {
            int idx = tid + it * 256;
            int j = idx / 64, c = idx % 64;
            int p = rev ? (LL - 1 - (t0 + j)) : (t0 + j);
            float v = xdbl[(size_t)(b * LL + p) * 64 + c];
            if (c < RR)            s_raw[j][c] = v;
            else if (c < RR + SSN) s_bc[j][c - RR].x = v;
            else                   s_bc[j][c - RR - SSN].y = v;
        }
        __syncthreads();

#pragma unroll
        for (int it = 0; it < SCH * SCD / 256; it++) {
            int idx = tid + it * 256;
            int j = idx / SCD;
            float u = mydtb;
#pragma unroll
            for (int k = 0; k < RR; k++) u = fmaf(s_raw[j][k], wdt[k], u);
            float sp = (u > 0.f) ? (u + log1pf(__expf(-u))) : log1pf(__expf(u));
            s_dx[j][mydl].x = sp;
        }
        __syncthreads();

#pragma unroll 8
        for (int j = 0; j < SCH; j++) {
            float2 dx = s_dx[j][cd];
            float2 bc = s_bc[j][s];
            float dA = __expf(dx.x * Aneg);
            h = fmaf(dA, h, dx.x * dx.y * bc.x);
            s_c[j][cd][s] = h * bc.y;
        }
        __syncthreads();

#pragma unroll
        for (int it = 0; it < SCH * SCD / 256; it++) {
            int idx = tid + it * 256;
            int j = idx / SCD, dl = idx % SCD;
            float sum = 0.f;
#pragma unroll
            for (int ss = 0; ss < SSN; ss++) sum += s_c[j][dl][ss];
            float y = fmaf(s_dx[j][dl].y, myD, sum);
            float zv = s_z[j][dl];
            y *= zv / (1.f + __expf(-zv));
            int p = rev ? (LL - 1 - (t0 + j)) : (t0 + j);
            yg[(size_t)(b * LL + p) * DI + d0 + dl] = __float2half(y);
        }
        __syncthreads();
    }
}

// ===========================================================================
// LayerNorm (optional fp16 copy of output), copy, zero, f2h convert
// ===========================================================================
__global__ void layernorm_kernel(const float* __restrict__ acc,
                                 const float* __restrict__ g,
                                 const float* __restrict__ bta,
                                 float* __restrict__ out,
                                 __half* __restrict__ out_h)
{
    __shared__ float red[256];
    int row = blockIdx.x;
    int t = threadIdx.x;
    const float* rp = acc + (size_t)row * NN;

    float v0 = rp[t];
    float v1 = rp[t + 256];

    red[t] = v0 + v1;
    __syncthreads();
    for (int o = 128; o > 0; o >>= 1) {
        if (t < o) red[t] += red[t + o];
        __syncthreads();
    }
    float mu = red[0] * (1.f / NN);
    __syncthreads();

    float c0 = v0 - mu, c1 = v1 - mu;
    red[t] = c0 * c0 + c1 * c1;
    __syncthreads();
    for (int o = 128; o > 0; o >>= 1) {
        if (t < o) red[t] += red[t + o];
        __syncthreads();
    }
    float inv = rsqrtf(red[0] * (1.f / NN) + EPS);

    float r0 = c0 * inv * g[t]       + bta[t];
    float r1 = c1 * inv * g[t + 256] + bta[t + 256];
    float* op = out + (size_t)row * NN;
    op[t]       = r0;
    op[t + 256] = r1;
    if (out_h) {
        __half* oh = out_h + (size_t)row * NN;
        oh[t]       = __float2half(r0);
        oh[t + 256] = __float2half(r1);
    }
}

__global__ void copy_kernel(float* __restrict__ dst, const float* __restrict__ src, int n4)
{
    int i = blockIdx.x * blockDim.x + threadIdx.x;
    if (i < n4) ((float4*)dst)[i] = ((const float4*)src)[i];
}

__global__ void zero_kernel(float* __restrict__ dst, int n4)
{
    int i = blockIdx.x * blockDim.x + threadIdx.x;
    if (i < n4) ((float4*)dst)[i] = make_float4(0.f, 0.f, 0.f, 0.f);
}

__global__ void f2h_kernel(const float* __restrict__ src, __half* __restrict__ dst, int n4)
{
    for (int i = blockIdx.x * blockDim.x + threadIdx.x; i < n4; i += gridDim.x * blockDim.x) {
        float4 v = ((const float4*)src)[i];
        ((__half2*)dst)[2 * i]     = __floats2half2_rn(v.x, v.y);
        ((__half2*)dst)[2 * i + 1] = __floats2half2_rn(v.z, v.w);
    }
}

// ===========================================================================
extern "C" void kernel_launch(void* const* d_in, const int* in_sizes, int n_in,
                              void* d_out, int out_size)
{
    const float* x    = (const float*)d_in[0];
    const float* inw  = (const float*)d_in[1];
    const float* cw   = (const float*)d_in[2];
    const float* cb   = (const float*)d_in[3];
    const float* xw   = (const float*)d_in[4];
    const float* dtw  = (const float*)d_in[5];
    const float* dtb  = (const float*)d_in[6];
    const float* Alog = (const float*)d_in[7];
    const float* Dp   = (const float*)d_in[8];
    const float* ow   = (const float*)d_in[9];
    const float* lng  = (const float*)d_in[10];
    const float* lnb  = (const float*)d_in[11];

    float *xz, *xc, *xdbl, *acc, *cur;
    __half *xh, *inwh, *owh, *ygh;
    cudaGetSymbolAddress((void**)&xz,   g_xz);
    cudaGetSymbolAddress((void**)&xc,   g_xc);
    cudaGetSymbolAddress((void**)&xdbl, g_xdbl);
    cudaGetSymbolAddress((void**)&acc,  g_acc);
    cudaGetSymbolAddress((void**)&cur,  g_cur);
    cudaGetSymbolAddress((void**)&xh,   g_xh);
    cudaGetSymbolAddress((void**)&inwh, g_inwh);
    cudaGetSymbolAddress((void**)&owh,  g_owh);
    cudaGetSymbolAddress((void**)&ygh,  g_ygh);

    static int smem_set = 0;
    if (!smem_set) {
        cudaFuncSetAttribute(hgemm_f16, cudaFuncAttributeMaxDynamicSharedMemorySize, HG_SMEM);
        smem_set = 1;
    }

    // One-pass fp16 conversion of weights and initial input (launches 1-3)
    f2h_kernel<<<592, 256>>>(x,   xh,   (int)(MROWS * NN / 4));
    f2h_kernel<<<592, 256>>>(inw, inwh, (int)(4 * 2 * DI * NN / 4));
    f2h_kernel<<<592, 256>>>(ow,  owh,  (int)(4 * NN * DI / 4));

    const float* layer_in = x;

    for (int l = 0; l < NLAYER; l++) {
        const size_t i0 = 2 * l;  // weight index of fwd direction

        // in_proj (launch 4 on first layer -> ncu captures it)
        hgemm_f16<<<dim3(2 * DI / 128, MROWS / 128, 2), 256, HG_SMEM>>>(
            xh, inwh + i0 * 2 * DI * NN, xz,
            NN, NN, NN, 2 * DI, /*epi*/0, /*nsplit*/1,
            0, (size_t)2 * DI * NN, XZ_SZ);

        // acc = residual (must precede out_proj atomics only)
        copy_kernel<<<(MROWS * NN / 4 + 255) / 256, 256>>>(acc, layer_in, MROWS * NN / 4);

        // conv + SiLU, both dirs
        conv_silu_kernel<<<dim3((BB * LL * DI / 4 + 255) / 256, 2), 256>>>(
            xz, cw + i0 * DI * KC, cb + i0 * DI, xc);

        // xproj, both dirs, split-K=8 + atomics
        zero_kernel<<<(2 * (int)XD_SZ / 4 + 255) / 256, 256>>>(xdbl, 2 * (int)XD_SZ / 4);
        sgemm_nt<64, 64, 16, 4, 4><<<dim3(1, MROWS / 64, 16), 256>>>(
            xc, xw + i0 * 64 * DI, xdbl,
            MROWS, 64, DI, DI, DI, 64, /*nsplit*/8,
            XC_SZ, (size_t)64 * DI, XD_SZ);

        // fused dtproj + scan + gate, both dirs -> fp16 yg
        scan_kernel<<<dim3(DI / SCD, BB, 2), 256>>>(
            xc, xz, xdbl,
            Alog + i0 * DI * SSN, Dp + i0 * DI,
            dtw + i0 * DI * RR, dtb + i0 * DI, ygh);

        // out_proj, both dirs x split-K=2, atomic into residual (fp16 operands)
        hgemm_f16<<<dim3(NN / 128, MROWS / 128, 4), 256, HG_SMEM>>>(
            ygh, owh + i0 * NN * DI, acc,
            DI, DI, DI, NN, /*epi*/2, /*nsplit*/2,
            YG_SZ, (size_t)NN * DI, 0);

        // LayerNorm; intermediate layer also emits fp16 input for next in_proj
        float* lnout = (l == NLAYER - 1) ? (float*)d_out : cur;
        __half* lnout_h = (l == NLAYER - 1) ? (__half*)nullptr : xh;
        layernorm_kernel<<<MROWS, 256>>>(acc, lng + (size_t)l * NN, lnb + (size_t)l * NN,
                                         lnout, lnout_h);
        layer_in = cur;
    }
}

// round 15
// speedup vs baseline: 1.0341x; 1.0338x over previous
#include <cuda_runtime.h>
#include <cuda_fp16.h>
#include <math.h>
#include <stdint.h>

// Problem constants
#define BB 2
#define LL 1024
#define NN 512
#define NLAYER 2
#define DI 1024
#define SSN 16
#define KC 4
#define RR 32
#define EPS 1e-5f
#define MROWS (BB*LL)   // 2048

// Per-direction buffer sizes (elements)
#define XZ_SZ ((size_t)MROWS * 2 * DI)
#define XC_SZ ((size_t)MROWS * DI)
#define XD_SZ ((size_t)MROWS * 64)
#define YG_SZ ((size_t)MROWS * DI)

// Scratch buffers (static device globals; no runtime allocation)
__device__ __align__(256) float  g_xz  [2 * XZ_SZ];
__device__ __align__(256) float  g_xc  [2 * XC_SZ];
__device__ __align__(256) float  g_xdbl[2 * XD_SZ];
__device__ __align__(256) float  g_acc [(size_t)MROWS * NN];
// fp16 operand buffers
__device__ __align__(256) __half g_xh  [(size_t)MROWS * NN];
__device__ __align__(256) __half g_inwh[(size_t)4 * 2 * DI * NN];
__device__ __align__(256) __half g_owh [(size_t)4 * NN * DI];
__device__ __align__(256) __half g_ygh [2 * YG_SZ];

// ===========================================================================
// Helpers
// ===========================================================================
static __device__ __forceinline__ uint32_t smem_u32(const void* p) {
    uint32_t a;
    asm("{ .reg .u64 t; cvta.to.shared.u64 t, %1; cvt.u32.u64 %0, t; }" : "=r"(a) : "l"(p));
    return a;
}

static __device__ __forceinline__ void ldsm4(uint32_t* r, uint32_t addr) {
    asm volatile("ldmatrix.sync.aligned.m8n8.x4.shared.b16 {%0,%1,%2,%3}, [%4];"
        : "=r"(r[0]), "=r"(r[1]), "=r"(r[2]), "=r"(r[3]) : "r"(addr));
}

static __device__ __forceinline__ void mma_f16(float* c, const uint32_t* a,
                                               uint32_t b0, uint32_t b1) {
    asm volatile(
        "mma.sync.aligned.m16n8k16.row.col.f32.f16.f16.f32 "
        "{%0,%1,%2,%3}, {%4,%5,%6,%7}, {%8,%9}, {%0,%1,%2,%3};"
        : "+f"(c[0]), "+f"(c[1]), "+f"(c[2]), "+f"(c[3])
        : "r"(a[0]), "r"(a[1]), "r"(a[2]), "r"(a[3]), "r"(b0), "r"(b1));
}

#define CP_ASYNC16(smem, gptr) \
    asm volatile("cp.async.cg.shared.global [%0], [%1], 16;" :: "r"(smem), "l"(gptr) : "memory")
#define CP_COMMIT() asm volatile("cp.async.commit_group;" ::: "memory")

// ===========================================================================
// Pure fp16 NT GEMM, K-chunk = 64, 3-stage cp.async, ONE sync per chunk.
// C[M,N] (+)= A[M,K] @ B[N,K]^T, fp16 in / fp32 out. Block 128x128, 8 warps.
// blockIdx.z = dir*nsplit + kslice; per-dir strides aZ/bZ/cZ (elements).
// epi: 0 = store, 2 = atomicAdd
// ===========================================================================
#define KCHUNK 64
#define PADH 72                          // 64 halfs + 8 pad (conflict-free LDSM)
#define TILEB (128 * PADH * 2)           // 18432 bytes per fp16 tile
#define NSTAGE 3
#define HG_SMEM (NSTAGE * 2 * TILEB)     // 110592 bytes

__global__ void __launch_bounds__(256, 2) hgemm_f16(
    const __half* __restrict__ A, const __half* __restrict__ Bw, float* __restrict__ C,
    int K, int lda, int ldb, int ldc, int epi, int nsplit,
    size_t aZ, size_t bZ, size_t cZ)
{
    extern __shared__ __align__(16) char dsm[];

    const int tid = threadIdx.x;
    const int wid = tid >> 5, lane = tid & 31;
    const int wm = wid >> 2, wn = wid & 3;
    const int bm = blockIdx.y * 128, bn = blockIdx.x * 128;
    const int dir = blockIdx.z / nsplit;
    const int ksl = blockIdx.z % nsplit;
    A  += (size_t)dir * aZ;
    Bw += (size_t)dir * bZ;
    C  += (size_t)dir * cZ;
    const int kslice = K / nsplit;
    const int kbeg = ksl * kslice;
    const int nch = kslice / KCHUNK;

    const uint32_t base = smem_u32(dsm);
    const int lrow = lane & 15;
    const int lchunk = lane >> 4;

    float acc[4][4][4];
#pragma unroll
    for (int i = 0; i < 4; i++)
#pragma unroll
        for (int j = 0; j < 4; j++)
#pragma unroll
            for (int q = 0; q < 4; q++) acc[i][j][q] = 0.f;

    auto issue_chunk = [&](int kc, int stg) {
        const __half* Ab = A + (size_t)bm * lda + kbeg + kc * KCHUNK;
        const __half* Bb = Bw + (size_t)bn * ldb + kbeg + kc * KCHUNK;
#pragma unroll
        for (int i = 0; i < 8; i++) {
            int op = tid + i * 256;            // 0..2047
            int tile = op >> 10;               // 0 = A, 1 = B
            int rem = op & 1023;
            int r = rem >> 3, seg = rem & 7;   // 8 x 16B segments per 128B row
            const __half* src = (tile ? Bb + (size_t)r * ldb : Ab + (size_t)r * lda) + seg * 8;
            uint32_t dst = base + (uint32_t)(stg * 2 + tile) * TILEB
                         + (uint32_t)(r * PADH + seg * 8) * 2;
            CP_ASYNC16(dst, src);
        }
        CP_COMMIT();
    };

    issue_chunk(0, 0);
    if (nch > 1) issue_chunk(1, 1);

    for (int kc = 0; kc < nch; kc++) {
        if (kc + 1 < nch) {
            asm volatile("cp.async.wait_group 1;" ::: "memory");
        } else {
            asm volatile("cp.async.wait_group 0;" ::: "memory");
        }
        __syncthreads();   // chunk kc visible; stage (kc+2)%3's old chunk consumed

        if (kc + 2 < nch) issue_chunk(kc + 2, (kc + 2) % NSTAGE);

        const uint32_t aA = base + (uint32_t)((kc % NSTAGE) * 2) * TILEB;
        const uint32_t aB = aA + TILEB;

#pragma unroll
        for (int ks = 0; ks < 4; ks++) {
            uint32_t ah[4][4];
#pragma unroll
            for (int mt = 0; mt < 4; mt++) {
                uint32_t off = (uint32_t)((wm * 64 + mt * 16 + lrow) * PADH
                                          + ks * 16 + lchunk * 8) * 2;
                ldsm4(ah[mt], aA + off);
            }
            uint32_t bh[2][4];
#pragma unroll
            for (int np = 0; np < 2; np++) {
                uint32_t off = (uint32_t)((wn * 32 + np * 16 + lrow) * PADH
                                          + ks * 16 + lchunk * 8) * 2;
                ldsm4(bh[np], aB + off);
            }
#pragma unroll
            for (int mt = 0; mt < 4; mt++)
#pragma unroll
                for (int np = 0; np < 2; np++)
#pragma unroll
                    for (int sub = 0; sub < 2; sub++) {
                        int nt = np * 2 + sub;
                        mma_f16(acc[mt][nt], ah[mt], bh[np][sub], bh[np][sub + 2]);
                    }
        }
    }

    // Epilogue
    const int r0 = lane >> 2;
    const int c0 = (lane & 3) * 2;
#pragma unroll
    for (int mt = 0; mt < 4; mt++) {
#pragma unroll
        for (int nt = 0; nt < 4; nt++) {
            int m = bm + wm * 64 + mt * 16 + r0;
            int n = bn + wn * 32 + nt * 8 + c0;
            float* p0 = &C[(size_t)m * ldc + n];
            float* p1 = &C[(size_t)(m + 8) * ldc + n];
            float* a = acc[mt][nt];
            if (epi == 0) {
                *(float2*)p0 = make_float2(a[0], a[1]);
                *(float2*)p1 = make_float2(a[2], a[3]);
            } else {
                atomicAdd(p0, a[0]); atomicAdd(p0 + 1, a[1]);
                atomicAdd(p1, a[2]); atomicAdd(p1 + 1, a[3]);
            }
        }
    }
}

// ===========================================================================
// CUDA-core SGEMM (xproj): split-K + atomicAdd. blockIdx.z = dir*nsplit + slice.
// ===========================================================================
template<int BM, int BN, int BK, int TM, int TN>
__global__ void sgemm_nt(const float* __restrict__ A, const float* __restrict__ Bm,
                         float* __restrict__ C, int M, int N, int Kt,
                         int lda, int ldb, int ldc, int nsplit,
                         size_t aZ, size_t bZ, size_t cZ)
{
    constexpr int TX = BN / TN;
    constexpr int TY = BM / TM;
    constexpr int THREADS = TX * TY;
    __shared__ float As[BK][BM + 4];
    __shared__ float Bs[BK][BN + 4];

    const int tid = threadIdx.x;
    const int tx = tid % TX;
    const int ty = tid / TX;
    const int bm = blockIdx.y * BM;
    const int bn = blockIdx.x * BN;
    const int dir = blockIdx.z / nsplit;
    const int ksl = blockIdx.z % nsplit;
    A += (size_t)dir * aZ;
    Bm += (size_t)dir * bZ;
    C += (size_t)dir * cZ;
    const int kslice = Kt / nsplit;
    const int kbeg = ksl * kslice;
    const int kend = kbeg + kslice;

    float acc[TM][TN];
#pragma unroll
    for (int m = 0; m < TM; m++)
#pragma unroll
        for (int n = 0; n < TN; n++) acc[m][n] = 0.f;

    for (int k0 = kbeg; k0 < kend; k0 += BK) {
#pragma unroll
        for (int i = 0; i < BM * BK / 4 / THREADS; i++) {
            int idx = tid + i * THREADS;
            int r = idx / (BK / 4);
            int c4 = idx % (BK / 4);
            float4 v = *(const float4*)&A[(size_t)(bm + r) * lda + k0 + c4 * 4];
            As[c4 * 4 + 0][r] = v.x;
            As[c4 * 4 + 1][r] = v.y;
            As[c4 * 4 + 2][r] = v.z;
            As[c4 * 4 + 3][r] = v.w;
        }
#pragma unroll
        for (int i = 0; i < BN * BK / 4 / THREADS; i++) {
            int idx = tid + i * THREADS;
            int r = idx / (BK / 4);
            int c4 = idx % (BK / 4);
            float4 v = *(const float4*)&Bm[(size_t)(bn + r) * ldb + k0 + c4 * 4];
            Bs[c4 * 4 + 0][r] = v.x;
            Bs[c4 * 4 + 1][r] = v.y;
            Bs[c4 * 4 + 2][r] = v.z;
            Bs[c4 * 4 + 3][r] = v.w;
        }
        __syncthreads();

#pragma unroll
        for (int k = 0; k < BK; k++) {
            float ra[TM], rb[TN];
#pragma unroll
            for (int m = 0; m < TM; m++) ra[m] = As[k][ty * TM + m];
#pragma unroll
            for (int n = 0; n < TN; n++) rb[n] = Bs[k][tx * TN + n];
#pragma unroll
            for (int m = 0; m < TM; m++)
#pragma unroll
                for (int n = 0; n < TN; n++)
                    acc[m][n] = fmaf(ra[m], rb[n], acc[m][n]);
        }
        __syncthreads();
    }

#pragma unroll
    for (int m = 0; m < TM; m++) {
        int r = bm + ty * TM + m;
#pragma unroll
        for (int n = 0; n < TN; n++) {
            int c = bn + tx * TN + n;
            atomicAdd(&C[(size_t)r * ldc + c], acc[m][n]);
        }
    }
}

// ===========================================================================
// Causal depthwise conv (K=4) + SiLU, float4 over d. blockIdx.y = dir.
// ===========================================================================
__global__ void conv_silu_kernel(const float* __restrict__ xz,
                                 const float* __restrict__ cw,
                                 const float* __restrict__ cb,
                                 float* __restrict__ xc)
{
    const int dir = blockIdx.y;
    xz += (size_t)dir * XZ_SZ;
    cw += (size_t)dir * DI * KC;
    cb += (size_t)dir * DI;
    xc += (size_t)dir * XC_SZ;
    const int rev = dir;

    int idx = blockIdx.x * blockDim.x + threadIdx.x;   // over B*L*DI/4
    if (idx >= BB * LL * DI / 4) return;
    int d4 = (idx % (DI / 4)) * 4;
    int l  = (idx / (DI / 4)) % LL;
    int b  = idx / ((DI / 4) * LL);

    float4 acc = *(const float4*)(cb + d4);
    float4 w0 = *(const float4*)(cw + (d4 + 0) * KC);
    float4 w1 = *(const float4*)(cw + (d4 + 1) * KC);
    float4 w2 = *(const float4*)(cw + (d4 + 2) * KC);
    float4 w3 = *(const float4*)(cw + (d4 + 3) * KC);
    const float wk0[4] = {w0.x, w0.y, w0.z, w0.w};
    const float wk1[4] = {w1.x, w1.y, w1.z, w1.w};
    const float wk2[4] = {w2.x, w2.y, w2.z, w2.w};
    const float wk3[4] = {w3.x, w3.y, w3.z, w3.w};

#pragma unroll
    for (int k = 0; k < KC; k++) {
        int lp = rev ? (l + (KC - 1) - k) : (l - (KC - 1) + k);
        if (lp >= 0 && lp < LL) {
            float4 v = *(const float4*)(xz + ((size_t)(b * LL + lp)) * 2 * DI + d4);
            acc.x = fmaf(wk0[k], v.x, acc.x);
            acc.y = fmaf(wk1[k], v.y, acc.y);
            acc.z = fmaf(wk2[k], v.z, acc.z);
            acc.w = fmaf(wk3[k], v.w, acc.w);
        }
    }
    acc.x *= 1.f / (1.f + __expf(-acc.x));
    acc.y *= 1.f / (1.f + __expf(-acc.y));
    acc.z *= 1.f / (1.f + __expf(-acc.z));
    acc.w *= 1.f / (1.f + __expf(-acc.w));
    *(float4*)(xc + (size_t)idx * 4) = acc;
}

// ===========================================================================
// Fused dtproj + softplus + selective scan + C-dot + D skip + SiLU(z) gate.
// Writes yg as fp16 (consumed only by out_proj hgemm_f16).
// ===========================================================================
#define SCH 32
#define SCD 16

__global__ void __launch_bounds__(256) scan_kernel(
                            const float* __restrict__ xc,
                            const float* __restrict__ xz,
                            const float* __restrict__ xdbl,
                            const float* __restrict__ Alog,
                            const float* __restrict__ Dp,
                            const float* __restrict__ dtw,
                            const float* __restrict__ dtb,
                            __half* __restrict__ yg)
{
    __shared__ float2 s_dx[SCH][SCD];
    __shared__ float  s_z [SCH][SCD];
    __shared__ float2 s_bc[SCH][SSN];
    __shared__ float  s_c [SCH][SCD][SSN + 1];
    float (*s_raw)[RR] = (float (*)[RR])(&s_c[0][0][0]);  // overlay, disjoint phases

    const int tid = threadIdx.x;
    const int cd = tid >> 4;
    const int s  = tid & 15;
    const int d0 = blockIdx.x * SCD;
    const int b  = blockIdx.y;
    const int dir = blockIdx.z;
    const int rev = dir;
    const int d  = d0 + cd;

    xc   += (size_t)dir * XC_SZ;
    xz   += (size_t)dir * XZ_SZ;
    xdbl += (size_t)dir * XD_SZ;
    yg   += (size_t)dir * YG_SZ;
    Alog += (size_t)dir * DI * SSN;
    Dp   += (size_t)dir * DI;
    dtw  += (size_t)dir * DI * RR;
    dtb  += (size_t)dir * DI;

    const float Aneg = -__expf(Alog[(size_t)d * SSN + s]);

    const int mydl = tid & 15;
    const float myD = Dp[d0 + mydl];
    float wdt[RR];
#pragma unroll
    for (int k = 0; k < RR; k++) wdt[k] = dtw[(size_t)(d0 + mydl) * RR + k];
    const float mydtb = dtb[d0 + mydl];

    float h = 0.f;

    for (int t0 = 0; t0 < LL; t0 += SCH) {
#pragma unroll
        for (int it = 0; it < SCH * SCD / 256; it++) {
            int idx = tid + it * 256;
            int j = idx / SCD, dl = idx % SCD;
            int p = rev ? (LL - 1 - (t0 + j)) : (t0 + j);
            size_t row = (size_t)(b * LL + p);
            s_dx[j][dl].y = xc[row * DI + d0 + dl];
            s_z [j][dl]   = xz[row * 2 * DI + DI + d0 + dl];
        }
#pragma unroll
        for (int it = 0; it < SCH * 64 / 256; it++) {
            int idx = tid + it * 256;
            int j = idx / 64, c = idx % 64;
            int p = rev ? (LL - 1 - (t0 + j)) : (t0 + j);
            float v = xdbl[(size_t)(b * LL + p) * 64 + c];
            if (c < RR)            s_raw[j][c] = v;
            else if (c < RR + SSN) s_bc[j][c - RR].x = v;
            else                   s_bc[j][c - RR - SSN].y = v;
        }
        __syncthreads();

#pragma unroll
        for (int it = 0; it < SCH * SCD / 256; it++) {
            int idx = tid + it * 256;
            int j = idx / SCD;
            float u = mydtb;
#pragma unroll
            for (int k = 0; k < RR; k++) u = fmaf(s_raw[j][k], wdt[k], u);
            float sp = (u > 0.f) ? (u + log1pf(__expf(-u))) : log1pf(__expf(u));
            s_dx[j][mydl].x = sp;
        }
        __syncthreads();

#pragma unroll 8
        for (int j = 0; j < SCH; j++) {
            float2 dx = s_dx[j][cd];
            float2 bc = s_bc[j][s];
            float dA = __expf(dx.x * Aneg);
            h = fmaf(dA, h, dx.x * dx.y * bc.x);
            s_c[j][cd][s] = h * bc.y;
        }
        __syncthreads();

#pragma unroll
        for (int it = 0; it < SCH * SCD / 256; it++) {
            int idx = tid + it * 256;
            int j = idx / SCD, dl = idx % SCD;
            float sum = 0.f;
#pragma unroll
            for (int ss = 0; ss < SSN; ss++) sum += s_c[j][dl][ss];
            float y = fmaf(s_dx[j][dl].y, myD, sum);
            float zv = s_z[j][dl];
            y *= zv / (1.f + __expf(-zv));
            int p = rev ? (LL - 1 - (t0 + j)) : (t0 + j);
            yg[(size_t)(b * LL + p) * DI + d0 + dl] = __float2half(y);
        }
        __syncthreads();
    }
}

// ===========================================================================
// LayerNorm: reads acc, writes fp32 result (may alias acc) + optional fp16.
// In-place safe: each thread loads its two elements before any write.
// ===========================================================================
__global__ void layernorm_kernel(const float* __restrict__ accp,
                                 const float* __restrict__ g,
                                 const float* __restrict__ bta,
                                 float* __restrict__ out,
                                 __half* __restrict__ out_h)
{
    __shared__ float red[256];
    int row = blockIdx.x;
    int t = threadIdx.x;
    const float* rp = accp + (size_t)row * NN;

    float v0 = rp[t];
    float v1 = rp[t + 256];

    red[t] = v0 + v1;
    __syncthreads();
    for (int o = 128; o > 0; o >>= 1) {
        if (t < o) red[t] += red[t + o];
        __syncthreads();
    }
    float mu = red[0] * (1.f / NN);
    __syncthreads();

    float c0 = v0 - mu, c1 = v1 - mu;
    red[t] = c0 * c0 + c1 * c1;
    __syncthreads();
    for (int o = 128; o > 0; o >>= 1) {
        if (t < o) red[t] += red[t + o];
        __syncthreads();
    }
    float inv = rsqrtf(red[0] * (1.f / NN) + EPS);

    float r0 = c0 * inv * g[t]       + bta[t];
    float r1 = c1 * inv * g[t + 256] + bta[t + 256];
    float* op = out + (size_t)row * NN;
    op[t]       = r0;
    op[t + 256] = r1;
    if (out_h) {
        __half* oh = out_h + (size_t)row * NN;
        oh[t]       = __float2half(r0);
        oh[t + 256] = __float2half(r1);
    }
}

__global__ void copy_kernel(float* __restrict__ dst, const float* __restrict__ src, int n4)
{
    int i = blockIdx.x * blockDim.x + threadIdx.x;
    if (i < n4) ((float4*)dst)[i] = ((const float4*)src)[i];
}

__global__ void zero_kernel(float* __restrict__ dst, int n4)
{
    int i = blockIdx.x * blockDim.x + threadIdx.x;
    if (i < n4) ((float4*)dst)[i] = make_float4(0.f, 0.f, 0.f, 0.f);
}

__global__ void f2h_kernel(const float* __restrict__ src, __half* __restrict__ dst, int n4)
{
    for (int i = blockIdx.x * blockDim.x + threadIdx.x; i < n4; i += gridDim.x * blockDim.x) {
        float4 v = ((const float4*)src)[i];
        ((__half2*)dst)[2 * i]     = __floats2half2_rn(v.x, v.y);
        ((__half2*)dst)[2 * i + 1] = __floats2half2_rn(v.z, v.w);
    }
}

// ===========================================================================
extern "C" void kernel_launch(void* const* d_in, const int* in_sizes, int n_in,
                              void* d_out, int out_size)
{
    const float* x    = (const float*)d_in[0];
    const float* inw  = (const float*)d_in[1];
    const float* cw   = (const float*)d_in[2];
    const float* cb   = (const float*)d_in[3];
    const float* xw   = (const float*)d_in[4];
    const float* dtw  = (const float*)d_in[5];
    const float* dtb  = (const float*)d_in[6];
    const float* Alog = (const float*)d_in[7];
    const float* Dp   = (const float*)d_in[8];
    const float* ow   = (const float*)d_in[9];
    const float* lng  = (const float*)d_in[10];
    const float* lnb  = (const float*)d_in[11];

    float *xz, *xc, *xdbl, *acc;
    __half *xh, *inwh, *owh, *ygh;
    cudaGetSymbolAddress((void**)&xz,   g_xz);
    cudaGetSymbolAddress((void**)&xc,   g_xc);
    cudaGetSymbolAddress((void**)&xdbl, g_xdbl);
    cudaGetSymbolAddress((void**)&acc,  g_acc);
    cudaGetSymbolAddress((void**)&xh,   g_xh);
    cudaGetSymbolAddress((void**)&inwh, g_inwh);
    cudaGetSymbolAddress((void**)&owh,  g_owh);
    cudaGetSymbolAddress((void**)&ygh,  g_ygh);

    static int smem_set = 0;
    if (!smem_set) {
        cudaFuncSetAttribute(hgemm_f16, cudaFuncAttributeMaxDynamicSharedMemorySize, HG_SMEM);
        smem_set = 1;
    }

    // One-pass fp16 conversion of weights and initial input (launches 1-3)
    f2h_kernel<<<592, 256>>>(x,   xh,   (int)(MROWS * NN / 4));
    f2h_kernel<<<592, 256>>>(inw, inwh, (int)(4 * 2 * DI * NN / 4));
    f2h_kernel<<<592, 256>>>(ow,  owh,  (int)(4 * NN * DI / 4));

    for (int l = 0; l < NLAYER; l++) {
        const size_t i0 = 2 * l;  // weight index of fwd direction

        // in_proj (launch 4 on first layer -> ncu captures it)
        hgemm_f16<<<dim3(2 * DI / 128, MROWS / 128, 2), 256, HG_SMEM>>>(
            xh, inwh + i0 * 2 * DI * NN, xz,
            NN, NN, NN, 2 * DI, /*epi*/0, /*nsplit*/1,
            0, (size_t)2 * DI * NN, XZ_SZ);

        // layer 0 residual init: acc = x (later layers: LN wrote acc in place)
        if (l == 0)
            copy_kernel<<<(MROWS * NN / 4 + 255) / 256, 256>>>(acc, x, MROWS * NN / 4);

        // conv + SiLU, both dirs
        conv_silu_kernel<<<dim3((BB * LL * DI / 4 + 255) / 256, 2), 256>>>(
            xz, cw + i0 * DI * KC, cb + i0 * DI, xc);

        // xproj, both dirs, split-K=8 + atomics
        zero_kernel<<<(2 * (int)XD_SZ / 4 + 255) / 256, 256>>>(xdbl, 2 * (int)XD_SZ / 4);
        sgemm_nt<64, 64, 16, 4, 4><<<dim3(1, MROWS / 64, 16), 256>>>(
            xc, xw + i0 * 64 * DI, xdbl,
            MROWS, 64, DI, DI, DI, 64, /*nsplit*/8,
            XC_SZ, (size_t)64 * DI, XD_SZ);

        // fused dtproj + scan + gate, both dirs -> fp16 yg
        scan_kernel<<<dim3(DI / SCD, BB, 2), 256>>>(
            xc, xz, xdbl,
            Alog + i0 * DI * SSN, Dp + i0 * DI,
            dtw + i0 * DI * RR, dtb + i0 * DI, ygh);

        // out_proj, both dirs x split-K=2, atomic into residual (fp16 operands)
        hgemm_f16<<<dim3(NN / 128, MROWS / 128, 4), 256, HG_SMEM>>>(
            ygh, owh + i0 * NN * DI, acc,
            DI, DI, DI, NN, /*epi*/2, /*nsplit*/2,
            YG_SZ, (size_t)NN * DI, 0);

        // LayerNorm: final layer -> d_out; else in-place into acc + fp16 xh
        if (l == NLAYER - 1) {
            layernorm_kernel<<<MROWS, 256>>>(acc, lng + (size_t)l * NN,
                                             lnb + (size_t)l * NN,
                                             (float*)d_out, (__half*)nullptr);
        } else {
            layernorm_kernel<<<MROWS, 256>>>(acc, lng + (size_t)l * NN,
                                             lnb + (size_t)l * NN,
                                             acc, xh);
        }
    }
}